// round 16
// baseline (speedup 1.0000x reference)
#include <cuda_runtime.h>
#include <cuda_bf16.h>
#include <cstdint>

#define Bsz   4
#define Cin   64
#define C2d   32
#define HW    16384
#define HW4   4096
#define NTI   32      // key tiles of 128
#define NSPL  2       // key splits

typedef unsigned int u32;

// Scratch (device globals)
__device__ __align__(1024) uint4 g_phH4[Bsz * HW4 * 4];        // fp16 phi, packed 64B/key
__device__ __align__(1024) uint4 g_gB4 [Bsz * HW4 * 4];        // bf16 g, packed 64B/key
__device__ __align__(1024) float g_yp  [NSPL * Bsz * HW * C2d];// unnormalized y partials
__device__ __align__(1024) float g_rs  [NSPL * Bsz * HW];      // partial row sums

// ---------------- helpers ----------------
__device__ __forceinline__ u32 smem_u32(const void* p) { return (u32)__cvta_generic_to_shared(p); }
__device__ __forceinline__ void cp16(u32 dst, const void* src) {
    asm volatile("cp.async.cg.shared.global [%0], [%1], 16;" :: "r"(dst), "l"(src));
}
__device__ __forceinline__ void cp_commit() { asm volatile("cp.async.commit_group;"); }
template <int N> __device__ __forceinline__ void cp_wait() {
    asm volatile("cp.async.wait_group %0;" :: "n"(N));
}
__device__ __forceinline__ void ldsm4(u32& r0, u32& r1, u32& r2, u32& r3, u32 a) {
    asm volatile("ldmatrix.sync.aligned.m8n8.x4.shared.b16 {%0,%1,%2,%3}, [%4];"
                 : "=r"(r0), "=r"(r1), "=r"(r2), "=r"(r3) : "r"(a));
}
__device__ __forceinline__ void ldsm4t(u32& r0, u32& r1, u32& r2, u32& r3, u32 a) {
    asm volatile("ldmatrix.sync.aligned.m8n8.x4.trans.shared.b16 {%0,%1,%2,%3}, [%4];"
                 : "=r"(r0), "=r"(r1), "=r"(r2), "=r"(r3) : "r"(a));
}
__device__ __forceinline__ u32 pbf2(float lo, float hi) {
    u32 r; asm("cvt.rn.bf16x2.f32 %0, %1, %2;" : "=r"(r) : "f"(hi), "f"(lo)); return r;
}
__device__ __forceinline__ u32 pf16(float lo, float hi) {
    u32 r; asm("cvt.rn.f16x2.f32 %0, %1, %2;" : "=r"(r) : "f"(hi), "f"(lo)); return r;
}
__device__ __forceinline__ float ex2f(float x) {
    float r; asm("ex2.approx.f32 %0, %1;" : "=f"(r) : "f"(x)); return r;
}
__device__ __forceinline__ void sts128(u32 a, u32 c0, u32 c1, u32 c2, u32 c3) {
    asm volatile("st.shared.v4.b32 [%0], {%1,%2,%3,%4};"
                 :: "r"(a), "r"(c0), "r"(c1), "r"(c2), "r"(c3) : "memory");
}
__device__ __forceinline__ void mma_f16(float* c, const u32* a, u32 b0, u32 b1) {
    asm volatile("mma.sync.aligned.m16n8k16.row.col.f32.f16.f16.f32 "
                 "{%0,%1,%2,%3}, {%4,%5,%6,%7}, {%8,%9}, {%0,%1,%2,%3};"
                 : "+f"(c[0]), "+f"(c[1]), "+f"(c[2]), "+f"(c[3])
                 : "r"(a[0]), "r"(a[1]), "r"(a[2]), "r"(a[3]), "r"(b0), "r"(b1));
}
__device__ __forceinline__ void mma_bf16(float* c, const u32* a, u32 b0, u32 b1) {
    asm volatile("mma.sync.aligned.m16n8k16.row.col.f32.bf16.bf16.f32 "
                 "{%0,%1,%2,%3}, {%4,%5,%6,%7}, {%8,%9}, {%0,%1,%2,%3};"
                 : "+f"(c[0]), "+f"(c[1]), "+f"(c[2]), "+f"(c[3])
                 : "r"(a[0]), "r"(a[1]), "r"(a[2]), "r"(a[3]), "r"(b0), "r"(b1));
}

// ===========================================================================
// Kernel 1: tensor-core conv1x1(phi & g) + 2x2 maxpool.
// One CTA = one batch image-row-pair (256 px). 256 thr (8 warps).
// out[64][256] = W2[64][64] x x[64][256]; pool on C-frags; pack to globals.
// SMEM: x fp16 [64c][256px] @0 (32K) | W fp16 [64o][64c] @32768 (8K) |
//       bias @40960 (256B) | pooled f32 [64 w2][68 pad] @41216 (17408B)
// ===========================================================================
#define CP_OFF_X  0
#define CP_OFF_W  32768
#define CP_OFF_B  40960
#define CP_OFF_P  41216
#define CP_SMEM   (41216 + 64 * 68 * 4)

__global__ void __launch_bounds__(256) conv_pool_mma_kernel(
    const float* __restrict__ x,
    const float* __restrict__ wphi, const float* __restrict__ bphi,
    const float* __restrict__ wg,   const float* __restrict__ bg)
{
    extern __shared__ __align__(1024) char smem[];
    float* smf = reinterpret_cast<float*>(smem);
    const u32 sb = smem_u32(smem);
    const int tid = threadIdx.x, wid = tid >> 5, lane = tid & 31;
    const int b = blockIdx.x >> 6;           // batch
    const int h2 = blockIdx.x & 63;          // pooled row
    const int n0 = h2 * 256;                 // first pixel of the row pair

    // ---- stage x [64c][256px] -> fp16, swizzled 512B rows ----
    {
        const float* xs = x + (size_t)b * Cin * HW + n0;
#pragma unroll
        for (int i = 0; i < 8; ++i) {
            int idx = tid + 256 * i;        // 2048 entries: c 0..63, oct 0..31
            int c = idx >> 5, oct = idx & 31;
            const float4* s = reinterpret_cast<const float4*>(xs + (size_t)c * HW + oct * 8);
            float4 v0 = s[0], v1 = s[1];
            u32 a = sb + CP_OFF_X + (u32)c * 512 + (u32)((oct ^ (c & 7)) * 16);
            sts128(a, pf16(v0.x, v0.y), pf16(v0.z, v0.w), pf16(v1.x, v1.y), pf16(v1.z, v1.w));
        }
    }
    // ---- stage W2 [64 out][64 c] fp16 (out<32: phi, else g), 128B rows ----
    {
        int o = tid >> 2, cq = tid & 3;
        const float* wsrc = (o < 32) ? (wphi + (size_t)o * Cin) : (wg + (size_t)(o - 32) * Cin);
        const float4* s = reinterpret_cast<const float4*>(wsrc + cq * 16);
        float4 v0 = s[0], v1 = s[1], v2 = s[2], v3 = s[3];
        u32 base = sb + CP_OFF_W + (u32)o * 128;
        sts128(base + (u32)(((2 * cq) ^ (o & 7)) * 16),
               pf16(v0.x, v0.y), pf16(v0.z, v0.w), pf16(v1.x, v1.y), pf16(v1.z, v1.w));
        sts128(base + (u32)(((2 * cq + 1) ^ (o & 7)) * 16),
               pf16(v2.x, v2.y), pf16(v2.z, v2.w), pf16(v3.x, v3.y), pf16(v3.z, v3.w));
    }
    if (tid < 32) {
        smf[CP_OFF_B / 4 + tid] = bphi[tid];
        smf[CP_OFF_B / 4 + 32 + tid] = bg[tid];
    }
    __syncthreads();

    // ---- MMA: warp = (mt = wid&3 out-tile, pq = wid>>2 px-half) ----
    const int mt = wid & 3, pq = wid >> 2;
    u32 af[4][4];
#pragma unroll
    for (int ks = 0; ks < 4; ++ks) {
        u32 row = (u32)(mt * 16 + ((lane >> 3) & 1) * 8 + (lane & 7));
        u32 ch = (u32)(2 * ks) + (u32)(lane >> 4);
        ldsm4(af[ks][0], af[ks][1], af[ks][2], af[ks][3],
              sb + CP_OFF_W + row * 128 + ((ch ^ (row & 7u)) * 16));
    }
    float acc[16][4];
#pragma unroll
    for (int i = 0; i < 16; ++i)
#pragma unroll
        for (int k = 0; k < 4; ++k) acc[i][k] = 0.f;

#pragma unroll
    for (int ip = 0; ip < 4; ++ip) {
#pragma unroll
        for (int hr = 0; hr < 2; ++hr) {
            const u32 jb = (u32)(hr * 16 + pq * 8 + 2 * ip);
#pragma unroll
            for (int ks = 0; ks < 4; ++ks) {
                u32 c = (u32)(16 * ks) + (u32)(lane & 15);
                u32 j = jb + (u32)(lane >> 4);
                u32 a = sb + CP_OFF_X + c * 512 + ((j ^ (c & 7u)) * 16);
                u32 b0, b1, b2, b3;
                ldsm4t(b0, b1, b2, b3, a);
                mma_f16(acc[hr * 8 + 2 * ip],     af[ks], b0, b1);
                mma_f16(acc[hr * 8 + 2 * ip + 1], af[ks], b2, b3);
            }
        }
    }

    // ---- 2x2 maxpool on fragments -> pooled smem [w2][68] ----
#pragma unroll
    for (int ib = 0; ib < 8; ++ib) {
        float m0 = fmaxf(fmaxf(acc[ib][0], acc[ib][1]),
                         fmaxf(acc[8 + ib][0], acc[8 + ib][1]));
        float m1 = fmaxf(fmaxf(acc[ib][2], acc[ib][3]),
                         fmaxf(acc[8 + ib][2], acc[8 + ib][3]));
        int w2 = pq * 32 + ib * 4 + (lane & 3);
        int o = mt * 16 + (lane >> 2);
        smf[CP_OFF_P / 4 + w2 * 68 + o] = m0;
        smf[CP_OFF_P / 4 + w2 * 68 + o + 8] = m1;
    }
    __syncthreads();

    // ---- pack: threads 0-63 phi(fp16), 64-127 g(bf16) ----
    if (tid < 128) {
        const int sel = tid >> 6, w2 = tid & 63;
        const int m = h2 * 64 + w2;
        const float* pv = smf + CP_OFF_P / 4 + w2 * 68 + sel * 32;
        const float* bo = smf + CP_OFF_B / 4 + sel * 32;
        float vals[32];
#pragma unroll
        for (int j = 0; j < 32; ++j) vals[j] = pv[j] + bo[j];

        uint4* base = (sel ? g_gB4 : g_phH4) + ((size_t)b * HW4 + (size_t)(m & ~127)) * 4;
        const int ml = m & 127, row = ml >> 1, half = ml & 1;
#pragma unroll
        for (int c = 0; c < 4; ++c) {
            uint4 v;
            if (sel) {
                v.x = pbf2(vals[8*c+0], vals[8*c+1]);
                v.y = pbf2(vals[8*c+2], vals[8*c+3]);
                v.z = pbf2(vals[8*c+4], vals[8*c+5]);
                v.w = pbf2(vals[8*c+6], vals[8*c+7]);
            } else {
                v.x = pf16(vals[8*c+0], vals[8*c+1]);
                v.y = pf16(vals[8*c+2], vals[8*c+3]);
                v.z = pf16(vals[8*c+4], vals[8*c+5]);
                v.w = pf16(vals[8*c+6], vals[8*c+7]);
            }
            int chunk = (half * 4 + c) ^ (row & 7);
            base[row * 8 + chunk] = v;
        }
    }
}

// ===========================================================================
// Kernel 2: fused theta-conv + flash attention (fp16 QK, bf16 PV), 2-way
// key split. grid=(128,4,2), 128 thr (4 warps x m32). 3 CTAs/SM (R11 config).
// ===========================================================================
#define OFF_Q    0
#define OFF_KV   8192
#define KVSTRIDE 16384
#define SMEM_AT  (8192 + 32768 + 8192)

__global__ void __launch_bounds__(128, 3) attn_fused_kernel(
    const float* __restrict__ x,
    const float* __restrict__ w_theta, const float* __restrict__ b_theta)
{
    extern __shared__ __align__(1024) char smem[];
    float* smf = reinterpret_cast<float*>(smem);
    const u32 sb = smem_u32(smem);
    const int tid = threadIdx.x, wid = tid >> 5, lane = tid & 31;
    const int b = blockIdx.y, q0 = blockIdx.x * 128;
    const int split = blockIdx.z;
    const int t0 = split * (NTI / NSPL), t1 = t0 + NTI / NSPL;
    const float LOG2E = 1.44269504088896340736f;

    // ---------------- Prologue: theta (x LOG2E, fp16) into Q smem ----------
    {
        const float* xs = x + (size_t)b * Cin * HW + q0;
#pragma unroll
        for (int i = 0; i < 16; ++i) {
            int idx = tid + 128 * i;
            int c = idx >> 5, off = idx & 31;
            cp16(sb + OFF_KV + (u32)idx * 16, xs + (size_t)c * HW + off * 4);
        }
        cp_commit();
#pragma unroll
        for (int i = 0; i < 16; ++i) {
            int idx = tid + 128 * i;
            int c = idx >> 5, o = idx & 31;
            smf[(OFF_KV + 32768) / 4 + idx] = w_theta[o * Cin + c];
        }
        cp_wait<0>();
        __syncthreads();

        const int p = tid;
        float acc[C2d];
#pragma unroll
        for (int j = 0; j < C2d; ++j) acc[j] = __ldg(b_theta + j);
        const float* xs_s = smf + OFF_KV / 4;
        const float* ws_s = smf + (OFF_KV + 32768) / 4;
#pragma unroll 4
        for (int c = 0; c < Cin; ++c) {
            float xv = xs_s[c * 128 + p];
            const float4* wr = reinterpret_cast<const float4*>(ws_s + c * 32);
#pragma unroll
            for (int k = 0; k < 8; ++k) {
                float4 wv = wr[k];
                acc[4*k+0] = fmaf(xv, wv.x, acc[4*k+0]);
                acc[4*k+1] = fmaf(xv, wv.y, acc[4*k+1]);
                acc[4*k+2] = fmaf(xv, wv.z, acc[4*k+2]);
                acc[4*k+3] = fmaf(xv, wv.w, acc[4*k+3]);
            }
        }
        const u32 prow = (u32)(p >> 1), phalf = (u32)(p & 1);
#pragma unroll
        for (int c = 0; c < 4; ++c) {
            u32 chunk = ((phalf * 4 + (u32)c) ^ (prow & 7u));
            u32 a = sb + OFF_Q + prow * 128 + chunk * 16;
            sts128(a, pf16(acc[8*c+0] * LOG2E, acc[8*c+1] * LOG2E),
                      pf16(acc[8*c+2] * LOG2E, acc[8*c+3] * LOG2E),
                      pf16(acc[8*c+4] * LOG2E, acc[8*c+5] * LOG2E),
                      pf16(acc[8*c+6] * LOG2E, acc[8*c+7] * LOG2E));
        }
        __syncthreads();
    }

    // ---------------- KV pipeline ----------------
    auto load_kv = [&](int t, int bufi) {
        u32 d = sb + OFF_KV + (u32)bufi * KVSTRIDE;
        const char* sp = (const char*)(g_phH4 + ((size_t)b * HW4 + (size_t)t * 128) * 4);
#pragma unroll
        for (int i = 0; i < 4; ++i) {
            int idx = tid + 128 * i;
            cp16(d + (u32)idx * 16, sp + (size_t)idx * 16);
        }
        const char* sg = (const char*)(g_gB4 + ((size_t)b * HW4 + (size_t)t * 128) * 4);
#pragma unroll
        for (int i = 0; i < 4; ++i) {
            int idx = tid + 128 * i;
            cp16(d + 8192 + (u32)idx * 16, sg + (size_t)idx * 16);
        }
    };
    load_kv(t0, 0);
    cp_commit();
    cp_wait<0>();
    __syncthreads();

    // Q A-frags (fp16 m16k16): 2 q-subblocks x 2 k-steps
    u32 qf[2][2][4];
#pragma unroll
    for (int qb = 0; qb < 2; ++qb)
#pragma unroll
    for (int ks = 0; ks < 2; ++ks) {
        u32 r = (u32)(32 * wid + 16 * qb + ((lane >> 3) & 1) * 8 + (lane & 7));
        u32 kc = (u32)(2 * ks) + (u32)(lane >> 4);
        u32 prow = r >> 1, phalf = r & 1u;
        u32 chunk = ((phalf * 4 + kc) ^ (prow & 7u));
        u32 a = sb + OFF_Q + prow * 128 + chunk * 16;
        ldsm4(qf[qb][ks][0], qf[qb][ks][1], qf[qb][ks][2], qf[qb][ks][3], a);
    }

    float ofrag[2][4][4];
#pragma unroll
    for (int qb = 0; qb < 2; ++qb)
#pragma unroll
    for (int nb = 0; nb < 4; ++nb)
#pragma unroll
        for (int i = 0; i < 4; ++i) ofrag[qb][nb][i] = 0.f;
    float rsum[2][2] = {{0.f, 0.f}, {0.f, 0.f}};

    int buf = 0;
    for (int t = t0; t < t1; ++t) {
        if (t + 1 < t1) { load_kv(t + 1, buf ^ 1); cp_commit(); cp_wait<1>(); }
        else            { cp_wait<0>(); }
        __syncthreads();

        const u32 Koff = sb + OFF_KV + (u32)buf * KVSTRIDE;
        const u32 Goff = Koff + 8192;

#pragma unroll
        for (int jp = 0; jp < 8; ++jp) {
            const u32 kb = (u32)(jp * 16);
            float s[2][2][4];
#pragma unroll
            for (int qb = 0; qb < 2; ++qb)
#pragma unroll
                for (int blk = 0; blk < 2; ++blk)
#pragma unroll
                    for (int i = 0; i < 4; ++i) s[qb][blk][i] = 0.f;

            {
                const u32 blk = (u32)(lane >> 4);
                const u32 kcs = (u32)((lane >> 3) & 1);
                const u32 n = kb + blk * 8 + (u32)(lane & 7);
                const u32 nrow = n >> 1, nhalf = n & 1u;
#pragma unroll
                for (int ks = 0; ks < 2; ++ks) {
                    u32 kc = (u32)(2 * ks) + kcs;
                    u32 chunk = ((nhalf * 4 + kc) ^ (nrow & 7u));
                    u32 a = Koff + nrow * 128 + chunk * 16;
                    u32 b0, b1, b2, b3;
                    ldsm4(b0, b1, b2, b3, a);
                    mma_f16(s[0][0], qf[0][ks], b0, b1);
                    mma_f16(s[1][0], qf[1][ks], b0, b1);
                    mma_f16(s[0][1], qf[0][ks], b2, b3);
                    mma_f16(s[1][1], qf[1][ks], b2, b3);
                }
            }

            u32 pa[2][4];
#pragma unroll
            for (int qb = 0; qb < 2; ++qb) {
                float e00 = ex2f(s[qb][0][0]), e01 = ex2f(s[qb][0][1]);
                float e02 = ex2f(s[qb][0][2]), e03 = ex2f(s[qb][0][3]);
                float e10 = ex2f(s[qb][1][0]), e11 = ex2f(s[qb][1][1]);
                float e12 = ex2f(s[qb][1][2]), e13 = ex2f(s[qb][1][3]);
                rsum[qb][0] += (e00 + e01) + (e10 + e11);
                rsum[qb][1] += (e02 + e03) + (e12 + e13);
                pa[qb][0] = pbf2(e00, e01);
                pa[qb][1] = pbf2(e02, e03);
                pa[qb][2] = pbf2(e10, e11);
                pa[qb][3] = pbf2(e12, e13);
            }

            const u32 key = kb + (u32)(lane & 15);
            const u32 grow = key >> 1, ghalf = key & 1u;
            const u32 nbhi = (u32)(lane >> 4);
#pragma unroll
            for (int nbb = 0; nbb < 4; nbb += 2) {
                u32 nbp = (u32)nbb + nbhi;
                u32 chunk = ((ghalf << 2) + nbp) ^ (grow & 7u);
                u32 ga = Goff + grow * 128 + chunk * 16;
                u32 g00, g01, g10, g11;
                ldsm4t(g00, g01, g10, g11, ga);
                mma_bf16(ofrag[0][nbb],     pa[0], g00, g01);
                mma_bf16(ofrag[1][nbb],     pa[1], g00, g01);
                mma_bf16(ofrag[0][nbb + 1], pa[0], g10, g11);
                mma_bf16(ofrag[1][nbb + 1], pa[1], g10, g11);
            }
        }
        __syncthreads();
        buf ^= 1;
    }

    // ---------------- store unnormalized partials ----------------
    const u32 qq = (u32)(lane & 3);
    float* ybase = g_yp + (size_t)split * (Bsz * HW * C2d);
#pragma unroll
    for (int qb = 0; qb < 2; ++qb) {
        float r0 = rsum[qb][0], r1 = rsum[qb][1];
        r0 += __shfl_xor_sync(0xFFFFFFFF, r0, 1);
        r0 += __shfl_xor_sync(0xFFFFFFFF, r0, 2);
        r1 += __shfl_xor_sync(0xFFFFFFFF, r1, 1);
        r1 += __shfl_xor_sync(0xFFFFFFFF, r1, 2);

        const int row0 = q0 + 32 * wid + 16 * qb + (lane >> 2);
        float* y0 = ybase + ((size_t)(b * HW + row0)) * C2d + 2 * qq;
        float* y1 = y0 + 8 * C2d;
#pragma unroll
        for (int nb = 0; nb < 4; ++nb) {
            *reinterpret_cast<float2*>(y0 + nb * 8) =
                make_float2(ofrag[qb][nb][0], ofrag[qb][nb][1]);
            *reinterpret_cast<float2*>(y1 + nb * 8) =
                make_float2(ofrag[qb][nb][2], ofrag[qb][nb][3]);
        }
        if (qq == 0) {
            g_rs[(size_t)split * (Bsz * HW) + b * HW + row0] = r0;
            g_rs[(size_t)split * (Bsz * HW) + b * HW + row0 + 8] = r1;
        }
    }
}

// ===========================================================================
// Kernel 3: combine partials + out-conv + residual. 2 threads per pixel.
// ===========================================================================
__global__ void __launch_bounds__(256) combine_out_kernel(
    const float* __restrict__ x, const float* __restrict__ w,
    const float* __restrict__ bias, float* __restrict__ out)
{
    __shared__ float ws[C2d * Cin];   // [c2][o]
    __shared__ float bs[Cin];
    const int tid = threadIdx.x;
    for (int i = tid; i < C2d * Cin; i += 256) { int c2 = i >> 6, o = i & 63; ws[i] = w[o * C2d + c2]; }
    if (tid < Cin) bs[tid] = bias[tid];
    __syncthreads();

    const int p = blockIdx.x * 128 + (tid & 127);
    const int h = tid >> 7;                      // output-channel half
    const int b = p >> 14, n = p & (HW - 1);

    const float inv = 1.0f / (g_rs[p] + g_rs[Bsz * HW + p]);
    float yv[C2d];
    {
        const float4* ya = reinterpret_cast<const float4*>(g_yp + (size_t)p * C2d);
        const float4* yb = reinterpret_cast<const float4*>(
            g_yp + (size_t)(Bsz * HW * C2d) + (size_t)p * C2d);
#pragma unroll
        for (int i = 0; i < 8; ++i) {
            float4 a = ya[i], bq = yb[i];
            yv[4*i+0] = (a.x + bq.x) * inv;
            yv[4*i+1] = (a.y + bq.y) * inv;
            yv[4*i+2] = (a.z + bq.z) * inv;
            yv[4*i+3] = (a.w + bq.w) * inv;
        }
    }

    float acc[32];
#pragma unroll
    for (int j = 0; j < 32; ++j) acc[j] = bs[h * 32 + j];
#pragma unroll 4
    for (int c2 = 0; c2 < C2d; ++c2) {
        float yc = yv[c2];
        const float4* wr = reinterpret_cast<const float4*>(ws + c2 * Cin + h * 32);
#pragma unroll
        for (int k = 0; k < 8; ++k) {
            float4 wv = wr[k];
            acc[4*k+0] = fmaf(yc, wv.x, acc[4*k+0]);
            acc[4*k+1] = fmaf(yc, wv.y, acc[4*k+1]);
            acc[4*k+2] = fmaf(yc, wv.z, acc[4*k+2]);
            acc[4*k+3] = fmaf(yc, wv.w, acc[4*k+3]);
        }
    }
    const float* xb = x + (size_t)b * Cin * HW + n;
    float* ob = out + (size_t)b * Cin * HW + n;
#pragma unroll
    for (int j = 0; j < 32; ++j) {
        int o = h * 32 + j;
        ob[(size_t)o * HW] = acc[j] + xb[(size_t)o * HW];
    }
}

// ===========================================================================
extern "C" void kernel_launch(void* const* d_in, const int* in_sizes, int n_in,
                              void* d_out, int out_size)
{
    const float* x       = (const float*)d_in[0];
    const float* w_theta = (const float*)d_in[1];
    const float* b_theta = (const float*)d_in[2];
    const float* w_phi   = (const float*)d_in[3];
    const float* b_phi   = (const float*)d_in[4];
    const float* w_g     = (const float*)d_in[5];
    const float* b_g     = (const float*)d_in[6];
    const float* w_out   = (const float*)d_in[7];
    const float* b_out   = (const float*)d_in[8];
    float* out = (float*)d_out;

    cudaFuncSetAttribute(conv_pool_mma_kernel,
                         cudaFuncAttributeMaxDynamicSharedMemorySize, CP_SMEM);
    conv_pool_mma_kernel<<<Bsz * 64, 256, CP_SMEM>>>(x, w_phi, b_phi, w_g, b_g);

    cudaFuncSetAttribute(attn_fused_kernel,
                         cudaFuncAttributeMaxDynamicSharedMemorySize, SMEM_AT);
    attn_fused_kernel<<<dim3(128, Bsz, NSPL), 128, SMEM_AT>>>(x, w_theta, b_theta);

    combine_out_kernel<<<(Bsz * HW) / 128, 256>>>(x, w_out, b_out, out);
}

// round 17
// speedup vs baseline: 1.0102x; 1.0102x over previous
#include <cuda_runtime.h>
#include <cuda_bf16.h>
#include <cstdint>

#define Bsz   4
#define Cin   64
#define C2d   32
#define HW    16384
#define HW4   4096
#define NTI   32      // key tiles of 128
#define NSPL  2       // key splits

typedef unsigned int u32;

// Scratch (device globals)
__device__ __align__(1024) uint4 g_phH4[Bsz * HW4 * 4];        // fp16 phi, packed 64B/key
__device__ __align__(1024) uint4 g_gB4 [Bsz * HW4 * 4];        // bf16 g, packed 64B/key
__device__ __align__(1024) float g_yp  [NSPL * Bsz * HW * C2d];// unnormalized y partials
__device__ __align__(1024) float g_rs  [NSPL * Bsz * HW];      // partial row sums

// ---------------- helpers ----------------
__device__ __forceinline__ u32 smem_u32(const void* p) { return (u32)__cvta_generic_to_shared(p); }
__device__ __forceinline__ void cp16(u32 dst, const void* src) {
    asm volatile("cp.async.cg.shared.global [%0], [%1], 16;" :: "r"(dst), "l"(src));
}
__device__ __forceinline__ void cp_commit() { asm volatile("cp.async.commit_group;"); }
template <int N> __device__ __forceinline__ void cp_wait() {
    asm volatile("cp.async.wait_group %0;" :: "n"(N));
}
__device__ __forceinline__ void ldsm4(u32& r0, u32& r1, u32& r2, u32& r3, u32 a) {
    asm volatile("ldmatrix.sync.aligned.m8n8.x4.shared.b16 {%0,%1,%2,%3}, [%4];"
                 : "=r"(r0), "=r"(r1), "=r"(r2), "=r"(r3) : "r"(a));
}
__device__ __forceinline__ void ldsm4t(u32& r0, u32& r1, u32& r2, u32& r3, u32 a) {
    asm volatile("ldmatrix.sync.aligned.m8n8.x4.trans.shared.b16 {%0,%1,%2,%3}, [%4];"
                 : "=r"(r0), "=r"(r1), "=r"(r2), "=r"(r3) : "r"(a));
}
__device__ __forceinline__ u32 pbf2(float lo, float hi) {
    u32 r; asm("cvt.rn.bf16x2.f32 %0, %1, %2;" : "=r"(r) : "f"(hi), "f"(lo)); return r;
}
__device__ __forceinline__ u32 pf16(float lo, float hi) {
    u32 r; asm("cvt.rn.f16x2.f32 %0, %1, %2;" : "=r"(r) : "f"(hi), "f"(lo)); return r;
}
__device__ __forceinline__ float ex2f(float x) {
    float r; asm("ex2.approx.f32 %0, %1;" : "=f"(r) : "f"(x)); return r;
}
__device__ __forceinline__ void sts128(u32 a, u32 c0, u32 c1, u32 c2, u32 c3) {
    asm volatile("st.shared.v4.b32 [%0], {%1,%2,%3,%4};"
                 :: "r"(a), "r"(c0), "r"(c1), "r"(c2), "r"(c3) : "memory");
}
__device__ __forceinline__ void mma_f16(float* c, const u32* a, u32 b0, u32 b1) {
    asm volatile("mma.sync.aligned.m16n8k16.row.col.f32.f16.f16.f32 "
                 "{%0,%1,%2,%3}, {%4,%5,%6,%7}, {%8,%9}, {%0,%1,%2,%3};"
                 : "+f"(c[0]), "+f"(c[1]), "+f"(c[2]), "+f"(c[3])
                 : "r"(a[0]), "r"(a[1]), "r"(a[2]), "r"(a[3]), "r"(b0), "r"(b1));
}
__device__ __forceinline__ void mma_bf16(float* c, const u32* a, u32 b0, u32 b1) {
    asm volatile("mma.sync.aligned.m16n8k16.row.col.f32.bf16.bf16.f32 "
                 "{%0,%1,%2,%3}, {%4,%5,%6,%7}, {%8,%9}, {%0,%1,%2,%3};"
                 : "+f"(c[0]), "+f"(c[1]), "+f"(c[2]), "+f"(c[3])
                 : "r"(a[0]), "r"(a[1]), "r"(a[2]), "r"(a[3]), "r"(b0), "r"(b1));
}

// ===========================================================================
// Kernel 1: tensor-core conv1x1(phi & g) + 2x2 maxpool.
// One CTA = one batch image-row-pair (256 px). 256 thr (8 warps).
// out[64][256] = W2[64][64] x x[64][256]; pool on C-frags; pack to globals.
// SMEM: x fp16 [64c][256px] @0 (32K) | W fp16 [64o][64c] @32768 (8K) |
//       bias @40960 (256B) | pooled f32 [64 w2][68 pad] @41216 (17408B)
// ===========================================================================
#define CP_OFF_X  0
#define CP_OFF_W  32768
#define CP_OFF_B  40960
#define CP_OFF_P  41216
#define CP_SMEM   (41216 + 64 * 68 * 4)

__global__ void __launch_bounds__(256) conv_pool_mma_kernel(
    const float* __restrict__ x,
    const float* __restrict__ wphi, const float* __restrict__ bphi,
    const float* __restrict__ wg,   const float* __restrict__ bg)
{
    extern __shared__ __align__(1024) char smem[];
    float* smf = reinterpret_cast<float*>(smem);
    const u32 sb = smem_u32(smem);
    const int tid = threadIdx.x, wid = tid >> 5, lane = tid & 31;
    const int b = blockIdx.x >> 6;           // batch
    const int h2 = blockIdx.x & 63;          // pooled row
    const int n0 = h2 * 256;                 // first pixel of the row pair

    // ---- stage x [64c][256px] -> fp16, swizzled 512B rows ----
    {
        const float* xs = x + (size_t)b * Cin * HW + n0;
#pragma unroll
        for (int i = 0; i < 8; ++i) {
            int idx = tid + 256 * i;        // 2048 entries: c 0..63, oct 0..31
            int c = idx >> 5, oct = idx & 31;
            const float4* s = reinterpret_cast<const float4*>(xs + (size_t)c * HW + oct * 8);
            float4 v0 = s[0], v1 = s[1];
            u32 a = sb + CP_OFF_X + (u32)c * 512 + (u32)((oct ^ (c & 7)) * 16);
            sts128(a, pf16(v0.x, v0.y), pf16(v0.z, v0.w), pf16(v1.x, v1.y), pf16(v1.z, v1.w));
        }
    }
    // ---- stage W2 [64 out][64 c] fp16 (out<32: phi, else g), 128B rows ----
    {
        int o = tid >> 2, cq = tid & 3;
        const float* wsrc = (o < 32) ? (wphi + (size_t)o * Cin) : (wg + (size_t)(o - 32) * Cin);
        const float4* s = reinterpret_cast<const float4*>(wsrc + cq * 16);
        float4 v0 = s[0], v1 = s[1], v2 = s[2], v3 = s[3];
        u32 base = sb + CP_OFF_W + (u32)o * 128;
        sts128(base + (u32)(((2 * cq) ^ (o & 7)) * 16),
               pf16(v0.x, v0.y), pf16(v0.z, v0.w), pf16(v1.x, v1.y), pf16(v1.z, v1.w));
        sts128(base + (u32)(((2 * cq + 1) ^ (o & 7)) * 16),
               pf16(v2.x, v2.y), pf16(v2.z, v2.w), pf16(v3.x, v3.y), pf16(v3.z, v3.w));
    }
    if (tid < 32) {
        smf[CP_OFF_B / 4 + tid] = bphi[tid];
        smf[CP_OFF_B / 4 + 32 + tid] = bg[tid];
    }
    __syncthreads();

    // ---- MMA: warp = (mt = wid&3 out-tile, pq = wid>>2 px-half) ----
    const int mt = wid & 3, pq = wid >> 2;
    u32 af[4][4];
#pragma unroll
    for (int ks = 0; ks < 4; ++ks) {
        u32 row = (u32)(mt * 16 + ((lane >> 3) & 1) * 8 + (lane & 7));
        u32 ch = (u32)(2 * ks) + (u32)(lane >> 4);
        ldsm4(af[ks][0], af[ks][1], af[ks][2], af[ks][3],
              sb + CP_OFF_W + row * 128 + ((ch ^ (row & 7u)) * 16));
    }
    float acc[16][4];
#pragma unroll
    for (int i = 0; i < 16; ++i)
#pragma unroll
        for (int k = 0; k < 4; ++k) acc[i][k] = 0.f;

#pragma unroll
    for (int ip = 0; ip < 4; ++ip) {
#pragma unroll
        for (int hr = 0; hr < 2; ++hr) {
            const u32 jb = (u32)(hr * 16 + pq * 8 + 2 * ip);
#pragma unroll
            for (int ks = 0; ks < 4; ++ks) {
                u32 c = (u32)(16 * ks) + (u32)(lane & 15);
                u32 j = jb + (u32)(lane >> 4);
                u32 a = sb + CP_OFF_X + c * 512 + ((j ^ (c & 7u)) * 16);
                u32 b0, b1, b2, b3;
                ldsm4t(b0, b1, b2, b3, a);
                mma_f16(acc[hr * 8 + 2 * ip],     af[ks], b0, b1);
                mma_f16(acc[hr * 8 + 2 * ip + 1], af[ks], b2, b3);
            }
        }
    }

    // ---- 2x2 maxpool on fragments -> pooled smem [w2][68] ----
#pragma unroll
    for (int ib = 0; ib < 8; ++ib) {
        float m0 = fmaxf(fmaxf(acc[ib][0], acc[ib][1]),
                         fmaxf(acc[8 + ib][0], acc[8 + ib][1]));
        float m1 = fmaxf(fmaxf(acc[ib][2], acc[ib][3]),
                         fmaxf(acc[8 + ib][2], acc[8 + ib][3]));
        int w2 = pq * 32 + ib * 4 + (lane & 3);
        int o = mt * 16 + (lane >> 2);
        smf[CP_OFF_P / 4 + w2 * 68 + o] = m0;
        smf[CP_OFF_P / 4 + w2 * 68 + o + 8] = m1;
    }
    __syncthreads();

    // ---- pack: threads 0-63 phi(fp16), 64-127 g(bf16) ----
    if (tid < 128) {
        const int sel = tid >> 6, w2 = tid & 63;
        const int m = h2 * 64 + w2;
        const float* pv = smf + CP_OFF_P / 4 + w2 * 68 + sel * 32;
        const float* bo = smf + CP_OFF_B / 4 + sel * 32;
        float vals[32];
#pragma unroll
        for (int j = 0; j < 32; ++j) vals[j] = pv[j] + bo[j];

        uint4* base = (sel ? g_gB4 : g_phH4) + ((size_t)b * HW4 + (size_t)(m & ~127)) * 4;
        const int ml = m & 127, row = ml >> 1, half = ml & 1;
#pragma unroll
        for (int c = 0; c < 4; ++c) {
            uint4 v;
            if (sel) {
                v.x = pbf2(vals[8*c+0], vals[8*c+1]);
                v.y = pbf2(vals[8*c+2], vals[8*c+3]);
                v.z = pbf2(vals[8*c+4], vals[8*c+5]);
                v.w = pbf2(vals[8*c+6], vals[8*c+7]);
            } else {
                v.x = pf16(vals[8*c+0], vals[8*c+1]);
                v.y = pf16(vals[8*c+2], vals[8*c+3]);
                v.z = pf16(vals[8*c+4], vals[8*c+5]);
                v.w = pf16(vals[8*c+6], vals[8*c+7]);
            }
            int chunk = (half * 4 + c) ^ (row & 7);
            base[row * 8 + chunk] = v;
        }
    }
}

// ===========================================================================
// Kernel 2: fused theta-conv + flash attention (fp16 QK, bf16 PV), 2-way
// key split. grid=(128,4,2), 128 thr (4 warps x m32). 3 CTAs/SM (R11 config).
// ===========================================================================
#define OFF_Q    0
#define OFF_KV   8192
#define KVSTRIDE 16384
#define SMEM_AT  (8192 + 32768 + 8192)

__global__ void __launch_bounds__(128, 3) attn_fused_kernel(
    const float* __restrict__ x,
    const float* __restrict__ w_theta, const float* __restrict__ b_theta)
{
    extern __shared__ __align__(1024) char smem[];
    float* smf = reinterpret_cast<float*>(smem);
    const u32 sb = smem_u32(smem);
    const int tid = threadIdx.x, wid = tid >> 5, lane = tid & 31;
    const int b = blockIdx.y, q0 = blockIdx.x * 128;
    const int split = blockIdx.z;
    const int t0 = split * (NTI / NSPL), t1 = t0 + NTI / NSPL;
    const float LOG2E = 1.44269504088896340736f;

    // ---------------- Prologue: theta (x LOG2E, fp16) into Q smem ----------
    {
        const float* xs = x + (size_t)b * Cin * HW + q0;
#pragma unroll
        for (int i = 0; i < 16; ++i) {
            int idx = tid + 128 * i;
            int c = idx >> 5, off = idx & 31;
            cp16(sb + OFF_KV + (u32)idx * 16, xs + (size_t)c * HW + off * 4);
        }
        cp_commit();
#pragma unroll
        for (int i = 0; i < 16; ++i) {
            int idx = tid + 128 * i;
            int c = idx >> 5, o = idx & 31;
            smf[(OFF_KV + 32768) / 4 + idx] = w_theta[o * Cin + c];
        }
        cp_wait<0>();
        __syncthreads();

        const int p = tid;
        float acc[C2d];
#pragma unroll
        for (int j = 0; j < C2d; ++j) acc[j] = __ldg(b_theta + j);
        const float* xs_s = smf + OFF_KV / 4;
        const float* ws_s = smf + (OFF_KV + 32768) / 4;
#pragma unroll 4
        for (int c = 0; c < Cin; ++c) {
            float xv = xs_s[c * 128 + p];
            const float4* wr = reinterpret_cast<const float4*>(ws_s + c * 32);
#pragma unroll
            for (int k = 0; k < 8; ++k) {
                float4 wv = wr[k];
                acc[4*k+0] = fmaf(xv, wv.x, acc[4*k+0]);
                acc[4*k+1] = fmaf(xv, wv.y, acc[4*k+1]);
                acc[4*k+2] = fmaf(xv, wv.z, acc[4*k+2]);
                acc[4*k+3] = fmaf(xv, wv.w, acc[4*k+3]);
            }
        }
        const u32 prow = (u32)(p >> 1), phalf = (u32)(p & 1);
#pragma unroll
        for (int c = 0; c < 4; ++c) {
            u32 chunk = ((phalf * 4 + (u32)c) ^ (prow & 7u));
            u32 a = sb + OFF_Q + prow * 128 + chunk * 16;
            sts128(a, pf16(acc[8*c+0] * LOG2E, acc[8*c+1] * LOG2E),
                      pf16(acc[8*c+2] * LOG2E, acc[8*c+3] * LOG2E),
                      pf16(acc[8*c+4] * LOG2E, acc[8*c+5] * LOG2E),
                      pf16(acc[8*c+6] * LOG2E, acc[8*c+7] * LOG2E));
        }
        __syncthreads();
    }

    // ---------------- KV pipeline ----------------
    auto load_kv = [&](int t, int bufi) {
        u32 d = sb + OFF_KV + (u32)bufi * KVSTRIDE;
        const char* sp = (const char*)(g_phH4 + ((size_t)b * HW4 + (size_t)t * 128) * 4);
#pragma unroll
        for (int i = 0; i < 4; ++i) {
            int idx = tid + 128 * i;
            cp16(d + (u32)idx * 16, sp + (size_t)idx * 16);
        }
        const char* sg = (const char*)(g_gB4 + ((size_t)b * HW4 + (size_t)t * 128) * 4);
#pragma unroll
        for (int i = 0; i < 4; ++i) {
            int idx = tid + 128 * i;
            cp16(d + 8192 + (u32)idx * 16, sg + (size_t)idx * 16);
        }
    };
    load_kv(t0, 0);
    cp_commit();
    cp_wait<0>();
    __syncthreads();

    // Q A-frags (fp16 m16k16): 2 q-subblocks x 2 k-steps
    u32 qf[2][2][4];
#pragma unroll
    for (int qb = 0; qb < 2; ++qb)
#pragma unroll
    for (int ks = 0; ks < 2; ++ks) {
        u32 r = (u32)(32 * wid + 16 * qb + ((lane >> 3) & 1) * 8 + (lane & 7));
        u32 kc = (u32)(2 * ks) + (u32)(lane >> 4);
        u32 prow = r >> 1, phalf = r & 1u;
        u32 chunk = ((phalf * 4 + kc) ^ (prow & 7u));
        u32 a = sb + OFF_Q + prow * 128 + chunk * 16;
        ldsm4(qf[qb][ks][0], qf[qb][ks][1], qf[qb][ks][2], qf[qb][ks][3], a);
    }

    float ofrag[2][4][4];
#pragma unroll
    for (int qb = 0; qb < 2; ++qb)
#pragma unroll
    for (int nb = 0; nb < 4; ++nb)
#pragma unroll
        for (int i = 0; i < 4; ++i) ofrag[qb][nb][i] = 0.f;
    float rsum[2][2] = {{0.f, 0.f}, {0.f, 0.f}};

    int buf = 0;
    for (int t = t0; t < t1; ++t) {
        if (t + 1 < t1) { load_kv(t + 1, buf ^ 1); cp_commit(); cp_wait<1>(); }
        else            { cp_wait<0>(); }
        __syncthreads();

        const u32 Koff = sb + OFF_KV + (u32)buf * KVSTRIDE;
        const u32 Goff = Koff + 8192;

#pragma unroll
        for (int jp = 0; jp < 8; ++jp) {
            const u32 kb = (u32)(jp * 16);
            float s[2][2][4];
#pragma unroll
            for (int qb = 0; qb < 2; ++qb)
#pragma unroll
                for (int blk = 0; blk < 2; ++blk)
#pragma unroll
                    for (int i = 0; i < 4; ++i) s[qb][blk][i] = 0.f;

            {
                const u32 blk = (u32)(lane >> 4);
                const u32 kcs = (u32)((lane >> 3) & 1);
                const u32 n = kb + blk * 8 + (u32)(lane & 7);
                const u32 nrow = n >> 1, nhalf = n & 1u;
#pragma unroll
                for (int ks = 0; ks < 2; ++ks) {
                    u32 kc = (u32)(2 * ks) + kcs;
                    u32 chunk = ((nhalf * 4 + kc) ^ (nrow & 7u));
                    u32 a = Koff + nrow * 128 + chunk * 16;
                    u32 b0, b1, b2, b3;
                    ldsm4(b0, b1, b2, b3, a);
                    mma_f16(s[0][0], qf[0][ks], b0, b1);
                    mma_f16(s[1][0], qf[1][ks], b0, b1);
                    mma_f16(s[0][1], qf[0][ks], b2, b3);
                    mma_f16(s[1][1], qf[1][ks], b2, b3);
                }
            }

            u32 pa[2][4];
#pragma unroll
            for (int qb = 0; qb < 2; ++qb) {
                float e00 = ex2f(s[qb][0][0]), e01 = ex2f(s[qb][0][1]);
                float e02 = ex2f(s[qb][0][2]), e03 = ex2f(s[qb][0][3]);
                float e10 = ex2f(s[qb][1][0]), e11 = ex2f(s[qb][1][1]);
                float e12 = ex2f(s[qb][1][2]), e13 = ex2f(s[qb][1][3]);
                rsum[qb][0] += (e00 + e01) + (e10 + e11);
                rsum[qb][1] += (e02 + e03) + (e12 + e13);
                pa[qb][0] = pbf2(e00, e01);
                pa[qb][1] = pbf2(e02, e03);
                pa[qb][2] = pbf2(e10, e11);
                pa[qb][3] = pbf2(e12, e13);
            }

            const u32 key = kb + (u32)(lane & 15);
            const u32 grow = key >> 1, ghalf = key & 1u;
            const u32 nbhi = (u32)(lane >> 4);
#pragma unroll
            for (int nbb = 0; nbb < 4; nbb += 2) {
                u32 nbp = (u32)nbb + nbhi;
                u32 chunk = ((ghalf << 2) + nbp) ^ (grow & 7u);
                u32 ga = Goff + grow * 128 + chunk * 16;
                u32 g00, g01, g10, g11;
                ldsm4t(g00, g01, g10, g11, ga);
                mma_bf16(ofrag[0][nbb],     pa[0], g00, g01);
                mma_bf16(ofrag[1][nbb],     pa[1], g00, g01);
                mma_bf16(ofrag[0][nbb + 1], pa[0], g10, g11);
                mma_bf16(ofrag[1][nbb + 1], pa[1], g10, g11);
            }
        }
        __syncthreads();
        buf ^= 1;
    }

    // ---------------- store unnormalized partials ----------------
    const u32 qq = (u32)(lane & 3);
    float* ybase = g_yp + (size_t)split * (Bsz * HW * C2d);
#pragma unroll
    for (int qb = 0; qb < 2; ++qb) {
        float r0 = rsum[qb][0], r1 = rsum[qb][1];
        r0 += __shfl_xor_sync(0xFFFFFFFF, r0, 1);
        r0 += __shfl_xor_sync(0xFFFFFFFF, r0, 2);
        r1 += __shfl_xor_sync(0xFFFFFFFF, r1, 1);
        r1 += __shfl_xor_sync(0xFFFFFFFF, r1, 2);

        const int row0 = q0 + 32 * wid + 16 * qb + (lane >> 2);
        float* y0 = ybase + ((size_t)(b * HW + row0)) * C2d + 2 * qq;
        float* y1 = y0 + 8 * C2d;
#pragma unroll
        for (int nb = 0; nb < 4; ++nb) {
            *reinterpret_cast<float2*>(y0 + nb * 8) =
                make_float2(ofrag[qb][nb][0], ofrag[qb][nb][1]);
            *reinterpret_cast<float2*>(y1 + nb * 8) =
                make_float2(ofrag[qb][nb][2], ofrag[qb][nb][3]);
        }
        if (qq == 0) {
            g_rs[(size_t)split * (Bsz * HW) + b * HW + row0] = r0;
            g_rs[(size_t)split * (Bsz * HW) + b * HW + row0 + 8] = r1;
        }
    }
}

// ===========================================================================
// Kernel 3: combine partials + out-conv + residual. 2 threads per pixel.
// ===========================================================================
__global__ void __launch_bounds__(256) combine_out_kernel(
    const float* __restrict__ x, const float* __restrict__ w,
    const float* __restrict__ bias, float* __restrict__ out)
{
    __shared__ float ws[C2d * Cin];   // [c2][o]
    __shared__ float bs[Cin];
    const int tid = threadIdx.x;
    for (int i = tid; i < C2d * Cin; i += 256) { int c2 = i >> 6, o = i & 63; ws[i] = w[o * C2d + c2]; }
    if (tid < Cin) bs[tid] = bias[tid];
    __syncthreads();

    const int p = blockIdx.x * 128 + (tid & 127);
    const int h = tid >> 7;                      // output-channel half
    const int b = p >> 14, n = p & (HW - 1);

    const float inv = 1.0f / (g_rs[p] + g_rs[Bsz * HW + p]);
    float yv[C2d];
    {
        const float4* ya = reinterpret_cast<const float4*>(g_yp + (size_t)p * C2d);
        const float4* yb = reinterpret_cast<const float4*>(
            g_yp + (size_t)(Bsz * HW * C2d) + (size_t)p * C2d);
#pragma unroll
        for (int i = 0; i < 8; ++i) {
            float4 a = ya[i], bq = yb[i];
            yv[4*i+0] = (a.x + bq.x) * inv;
            yv[4*i+1] = (a.y + bq.y) * inv;
            yv[4*i+2] = (a.z + bq.z) * inv;
            yv[4*i+3] = (a.w + bq.w) * inv;
        }
    }

    float acc[32];
#pragma unroll
    for (int j = 0; j < 32; ++j) acc[j] = bs[h * 32 + j];
#pragma unroll 4
    for (int c2 = 0; c2 < C2d; ++c2) {
        float yc = yv[c2];
        const float4* wr = reinterpret_cast<const float4*>(ws + c2 * Cin + h * 32);
#pragma unroll
        for (int k = 0; k < 8; ++k) {
            float4 wv = wr[k];
            acc[4*k+0] = fmaf(yc, wv.x, acc[4*k+0]);
            acc[4*k+1] = fmaf(yc, wv.y, acc[4*k+1]);
            acc[4*k+2] = fmaf(yc, wv.z, acc[4*k+2]);
            acc[4*k+3] = fmaf(yc, wv.w, acc[4*k+3]);
        }
    }
    const float* xb = x + (size_t)b * Cin * HW + n;
    float* ob = out + (size_t)b * Cin * HW + n;
#pragma unroll
    for (int j = 0; j < 32; ++j) {
        int o = h * 32 + j;
        ob[(size_t)o * HW] = acc[j] + xb[(size_t)o * HW];
    }
}

// ===========================================================================
extern "C" void kernel_launch(void* const* d_in, const int* in_sizes, int n_in,
                              void* d_out, int out_size)
{
    const float* x       = (const float*)d_in[0];
    const float* w_theta = (const float*)d_in[1];
    const float* b_theta = (const float*)d_in[2];
    const float* w_phi   = (const float*)d_in[3];
    const float* b_phi   = (const float*)d_in[4];
    const float* w_g     = (const float*)d_in[5];
    const float* b_g     = (const float*)d_in[6];
    const float* w_out   = (const float*)d_in[7];
    const float* b_out   = (const float*)d_in[8];
    float* out = (float*)d_out;

    cudaFuncSetAttribute(conv_pool_mma_kernel,
                         cudaFuncAttributeMaxDynamicSharedMemorySize, CP_SMEM);
    conv_pool_mma_kernel<<<Bsz * 64, 256, CP_SMEM>>>(x, w_phi, b_phi, w_g, b_g);

    cudaFuncSetAttribute(attn_fused_kernel,
                         cudaFuncAttributeMaxDynamicSharedMemorySize, SMEM_AT);
    attn_fused_kernel<<<dim3(128, Bsz, NSPL), 128, SMEM_AT>>>(x, w_theta, b_theta);

    combine_out_kernel<<<(Bsz * HW) / 128, 256>>>(x, w_out, b_out, out);
}